// round 1
// baseline (speedup 1.0000x reference)
#include <cuda_runtime.h>
#include <cstdint>

#define N_ROWS  16384
#define D_DIM   512
#define K_CODES 8192

#define BM 64      // rows of x per block
#define BK 128     // codebook columns per chunk
#define BD 8       // depth step

// -------- device scratch (no allocations allowed) --------
__device__ float g_wnorm[K_CODES];
__device__ int   g_idx[N_ROWS];
__device__ float g_loss;

// ============================================================
// Kernel 1: wnorm[k] = ||W_k||^2 ; also zero the loss accumulator
// ============================================================
__global__ void wnorm_kernel(const float* __restrict__ W) {
    int k = blockIdx.x;
    const float* row = W + (size_t)k * D_DIM;
    float s = 0.f;
    // 128 threads, 4 floats each via float4
    int d = threadIdx.x * 4;
    float4 v = *reinterpret_cast<const float4*>(row + d);
    s = v.x * v.x + v.y * v.y + v.z * v.z + v.w * v.w;
    #pragma unroll
    for (int o = 16; o > 0; o >>= 1) s += __shfl_xor_sync(0xffffffffu, s, o);
    __shared__ float sm[4];
    if ((threadIdx.x & 31) == 0) sm[threadIdx.x >> 5] = s;
    __syncthreads();
    if (threadIdx.x == 0) {
        g_wnorm[k] = sm[0] + sm[1] + sm[2] + sm[3];
        if (k == 0) g_loss = 0.f;   // zero accumulator every launch (graph-safe)
    }
}

// ============================================================
// Kernel 2: fused GEMM + argmax of (x.w - 0.5*||w||^2)
// Block: 64 rows of x, sweeps all K columns in chunks of 128.
// 256 threads; each computes a 4x8 microtile.
// ============================================================
__global__ void __launch_bounds__(256, 2)
argmin_kernel(const float* __restrict__ X, const float* __restrict__ W) {
    __shared__ float xs[BD][BM + 4];   // stride 68 floats = 272B (16B-aligned)
    __shared__ float ws[BD][BK + 4];   // stride 132 floats = 528B (16B-aligned)
    __shared__ float rv[16][16];
    __shared__ int   ri[16][16];

    const int tid = threadIdx.x;
    const int tx = tid & 15;    // column group: cols tx*8 .. tx*8+7
    const int ty = tid >> 4;    // row group:    rows ty*4 .. ty*4+3
    const int row0 = blockIdx.x * BM;

    float best[4];
    int   bidx[4];
    #pragma unroll
    for (int i = 0; i < 4; i++) { best[i] = -3.4e38f; bidx[i] = 0; }

    for (int kc = 0; kc < K_CODES; kc += BK) {
        float acc[4][8];
        #pragma unroll
        for (int i = 0; i < 4; i++)
            #pragma unroll
            for (int j = 0; j < 8; j++) acc[i][j] = 0.f;

        for (int d0 = 0; d0 < D_DIM; d0 += BD) {
            // ---- load x tile (64 rows x 8 depth), transposed into xs[d][row]
            if (tid < 128) {
                int r = tid >> 1, dp = tid & 1;
                float4 v = *reinterpret_cast<const float4*>(
                    X + (size_t)(row0 + r) * D_DIM + d0 + dp * 4);
                xs[dp * 4 + 0][r] = v.x;
                xs[dp * 4 + 1][r] = v.y;
                xs[dp * 4 + 2][r] = v.z;
                xs[dp * 4 + 3][r] = v.w;
            }
            // ---- load W tile (128 cols x 8 depth), transposed into ws[d][col]
            {
                int c = tid >> 1, dp = tid & 1;
                float4 v = *reinterpret_cast<const float4*>(
                    W + (size_t)(kc + c) * D_DIM + d0 + dp * 4);
                ws[dp * 4 + 0][c] = v.x;
                ws[dp * 4 + 1][c] = v.y;
                ws[dp * 4 + 2][c] = v.z;
                ws[dp * 4 + 3][c] = v.w;
            }
            __syncthreads();

            #pragma unroll
            for (int d = 0; d < BD; d++) {
                float a[4], b[8];
                *reinterpret_cast<float4*>(a)     = *reinterpret_cast<const float4*>(&xs[d][ty * 4]);
                *reinterpret_cast<float4*>(b)     = *reinterpret_cast<const float4*>(&ws[d][tx * 8]);
                *reinterpret_cast<float4*>(b + 4) = *reinterpret_cast<const float4*>(&ws[d][tx * 8 + 4]);
                #pragma unroll
                for (int i = 0; i < 4; i++)
                    #pragma unroll
                    for (int j = 0; j < 8; j++)
                        acc[i][j] = fmaf(a[i], b[j], acc[i][j]);
            }
            __syncthreads();
        }

        // ---- chunk epilogue: score = dot - 0.5*wnorm, running argmax
        #pragma unroll
        for (int j = 0; j < 8; j++) {
            int col = kc + tx * 8 + j;
            float half_wn = 0.5f * __ldg(&g_wnorm[col]);
            #pragma unroll
            for (int i = 0; i < 4; i++) {
                float m = acc[i][j] - half_wn;
                if (m > best[i]) { best[i] = m; bidx[i] = col; }  // strict > => first index wins
            }
        }
    }

    // ---- cross-thread (over tx) argmax per row; ascending tx => ascending col, strict >
    #pragma unroll
    for (int i = 0; i < 4; i++) {
        __syncthreads();
        rv[ty][tx] = best[i];
        ri[ty][tx] = bidx[i];
        __syncthreads();
        if (tx == 0) {
            float bv = rv[ty][0];
            int   bi = ri[ty][0];
            #pragma unroll
            for (int t = 1; t < 16; t++) {
                if (rv[ty][t] > bv) { bv = rv[ty][t]; bi = ri[ty][t]; }
            }
            g_idx[row0 + ty * 4 + i] = bi;
        }
    }
}

// ============================================================
// Kernel 3: gather W[idx[n]] -> out row n ; accumulate sum((q-x)^2)
// ============================================================
__global__ void gather_kernel(const float* __restrict__ X,
                              const float* __restrict__ W,
                              float* __restrict__ out) {
    int n = blockIdx.x;
    int k = g_idx[n];
    const float* wr = W + (size_t)k * D_DIM;
    const float* xr = X + (size_t)n * D_DIM;
    float* orow = out + (size_t)n * D_DIM;

    int d = threadIdx.x * 4;   // 128 threads x float4 = 512
    float4 q  = *reinterpret_cast<const float4*>(wr + d);
    float4 xv = *reinterpret_cast<const float4*>(xr + d);
    *reinterpret_cast<float4*>(orow + d) = q;
    float dx = q.x - xv.x, dy = q.y - xv.y, dz = q.z - xv.z, dw = q.w - xv.w;
    float s = dx * dx + dy * dy + dz * dz + dw * dw;

    #pragma unroll
    for (int o = 16; o > 0; o >>= 1) s += __shfl_xor_sync(0xffffffffu, s, o);
    __shared__ float sm[4];
    if ((threadIdx.x & 31) == 0) sm[threadIdx.x >> 5] = s;
    __syncthreads();
    if (threadIdx.x == 0) {
        atomicAdd(&g_loss, sm[0] + sm[1] + sm[2] + sm[3]);
    }
}

// ============================================================
// Kernel 4: finalize loss: vq_loss = 1.25 * mean((q-x)^2)
// ============================================================
__global__ void loss_kernel(float* __restrict__ out, int pos) {
    out[pos] = 1.25f * g_loss / (float)(N_ROWS * D_DIM);
}

// ============================================================
extern "C" void kernel_launch(void* const* d_in, const int* in_sizes, int n_in,
                              void* d_out, int out_size) {
    const float* x = (const float*)d_in[0];
    const float* W = (const float*)d_in[1];
    // defensive: metadata order should be (x, W); swap if sizes say otherwise
    if (in_sizes[0] == K_CODES * D_DIM && in_sizes[1] == N_ROWS * D_DIM) {
        const float* t = x; x = W; W = t;
    }
    float* out = (float*)d_out;

    wnorm_kernel <<<K_CODES, 128>>>(W);
    argmin_kernel<<<N_ROWS / BM, 256>>>(x, W);
    gather_kernel<<<N_ROWS, 128>>>(x, W, out);
    loss_kernel  <<<1, 1>>>(out, out_size - 1);
}

// round 5
// speedup vs baseline: 3.3286x; 3.3286x over previous
#include <cuda_runtime.h>
#include <cuda_bf16.h>
#include <cstdint>

#define N_ROWS  16384
#define D_DIM   512
#define K_CODES 8192

#define BM 128
#define BN 128
#define KC 32            // depth per chunk
#define NKC 16           // 512/32
#define NTILE 64         // 8192/128
#define STAGES 3
#define PITCH_B 80       // bytes per smem row (40 bf16, conflict-free for ldmatrix)
#define TILE_BYTES 10240 // 128 * 80
#define STAGE_BYTES 40960
#define SMEM_DYN (STAGES * STAGE_BYTES)

// ---------------- device scratch (static: no allocations) ----------------
__device__ __nv_bfloat16 g_xhi[N_ROWS * D_DIM];
__device__ __nv_bfloat16 g_xlo[N_ROWS * D_DIM];
__device__ __nv_bfloat16 g_whi[K_CODES * D_DIM];
__device__ __nv_bfloat16 g_wlo[K_CODES * D_DIM];
__device__ float g_wnorm[K_CODES];
__device__ int2  g_cand[N_ROWS];
__device__ int   g_idx[N_ROWS];
__device__ float g_loss;

// ---------------- helpers ----------------
__device__ __forceinline__ uint32_t smem_u32(const void* p) {
    uint32_t a;
    asm("{ .reg .u64 t; cvta.to.shared.u64 t, %1; cvt.u32.u64 %0, t; }" : "=r"(a) : "l"(p));
    return a;
}

__device__ __forceinline__ void split4(float4 v, uint32_t& h0, uint32_t& h1,
                                       uint32_t& l0, uint32_t& l1) {
    asm("cvt.rn.bf16x2.f32 %0, %1, %2;" : "=r"(h0) : "f"(v.y), "f"(v.x));
    asm("cvt.rn.bf16x2.f32 %0, %1, %2;" : "=r"(h1) : "f"(v.w), "f"(v.z));
    float hx = __uint_as_float(h0 << 16);
    float hy = __uint_as_float(h0 & 0xffff0000u);
    float hz = __uint_as_float(h1 << 16);
    float hw = __uint_as_float(h1 & 0xffff0000u);
    float lx = v.x - hx, ly = v.y - hy, lz = v.z - hz, lw = v.w - hw;
    asm("cvt.rn.bf16x2.f32 %0, %1, %2;" : "=r"(l0) : "f"(ly), "f"(lx));
    asm("cvt.rn.bf16x2.f32 %0, %1, %2;" : "=r"(l1) : "f"(lw), "f"(lz));
}

__device__ __forceinline__ void ldsm4(uint32_t* r, uint32_t addr) {
    asm volatile("ldmatrix.sync.aligned.m8n8.x4.shared.b16 {%0,%1,%2,%3}, [%4];"
                 : "=r"(r[0]), "=r"(r[1]), "=r"(r[2]), "=r"(r[3]) : "r"(addr));
}

__device__ __forceinline__ void mma16816(float* c, const uint32_t* a,
                                         uint32_t b0, uint32_t b1) {
    asm volatile(
        "mma.sync.aligned.m16n8k16.row.col.f32.bf16.bf16.f32 "
        "{%0,%1,%2,%3}, {%4,%5,%6,%7}, {%8,%9}, {%0,%1,%2,%3};"
        : "+f"(c[0]), "+f"(c[1]), "+f"(c[2]), "+f"(c[3])
        : "r"(a[0]), "r"(a[1]), "r"(a[2]), "r"(a[3]), "r"(b0), "r"(b1));
}

#define CP_ASYNC16(dst, src) \
    asm volatile("cp.async.cg.shared.global [%0], [%1], 16;" :: "r"(dst), "l"(src))
#define CP_COMMIT()   asm volatile("cp.async.commit_group;" ::: "memory")
#define CP_WAIT(n)    asm volatile("cp.async.wait_group %0;" :: "n"(n) : "memory")

// ============================================================
// split kernels: fp32 -> bf16 hi/lo planes
// ============================================================
__global__ void split_x_kernel(const float* __restrict__ src) {
    int i = blockIdx.x * blockDim.x + threadIdx.x;   // over float4s
    float4 v = reinterpret_cast<const float4*>(src)[i];
    uint32_t h0, h1, l0, l1;
    split4(v, h0, h1, l0, l1);
    reinterpret_cast<uint2*>(g_xhi)[i] = make_uint2(h0, h1);
    reinterpret_cast<uint2*>(g_xlo)[i] = make_uint2(l0, l1);
}
__global__ void split_w_kernel(const float* __restrict__ src) {
    int i = blockIdx.x * blockDim.x + threadIdx.x;
    float4 v = reinterpret_cast<const float4*>(src)[i];
    uint32_t h0, h1, l0, l1;
    split4(v, h0, h1, l0, l1);
    reinterpret_cast<uint2*>(g_whi)[i] = make_uint2(h0, h1);
    reinterpret_cast<uint2*>(g_wlo)[i] = make_uint2(l0, l1);
}

// ============================================================
// wnorm + zero loss
// ============================================================
__global__ void wnorm_kernel(const float* __restrict__ W) {
    int k = blockIdx.x;
    const float* row = W + (size_t)k * D_DIM;
    int d = threadIdx.x * 4;
    float4 v = *reinterpret_cast<const float4*>(row + d);
    float s = v.x * v.x + v.y * v.y + v.z * v.z + v.w * v.w;
    #pragma unroll
    for (int o = 16; o > 0; o >>= 1) s += __shfl_xor_sync(0xffffffffu, s, o);
    __shared__ float sm[4];
    if ((threadIdx.x & 31) == 0) sm[threadIdx.x >> 5] = s;
    __syncthreads();
    if (threadIdx.x == 0) {
        g_wnorm[k] = sm[0] + sm[1] + sm[2] + sm[3];
        if (k == 0) g_loss = 0.f;
    }
}

// ============================================================
// fused split-bf16 HMMA GEMM + top-2 argmax
// grid = 128 row tiles, 256 threads (8 warps, 2x4)
// ============================================================
__global__ void __launch_bounds__(256, 1)
argmin_mma() {
    extern __shared__ __align__(16) char smem[];
    const uint32_t sb = smem_u32(smem);
    const int tid  = threadIdx.x;
    const int lane = tid & 31;
    const int wid  = tid >> 5;
    const int wm = wid >> 2;          // 0..1 : 64-row slab
    const int wn = wid & 3;           // 0..3 : 32-col slab
    const int row0 = blockIdx.x * BM;

    // cp.async role: 4 arrays x 64 threads
    const int larr = tid >> 6;        // 0:Ahi 1:Alo 2:Bhi 3:Blo
    const int lthr = tid & 63;
    const bool isA = larr < 2;
    const __nv_bfloat16* srcbase =
        (larr == 0) ? g_xhi : (larr == 1) ? g_xlo : (larr == 2) ? g_whi : g_wlo;

    const uint32_t lm_off = (uint32_t)((lane & 15) * PITCH_B + (lane >> 4) * 16);
    const uint32_t a_base_row = (uint32_t)(wm * 64) * PITCH_B;
    const uint32_t b_base_row = (uint32_t)(wn * 32) * PITCH_B;

    float acc[4][4][4];
    #pragma unroll
    for (int am = 0; am < 4; ++am)
        #pragma unroll
        for (int an = 0; an < 4; ++an)
            #pragma unroll
            for (int j = 0; j < 4; ++j) acc[am][an][j] = 0.f;

    // per-thread top-2 per (am, h) row
    float b1[4][2], b2[4][2];
    int   i1[4][2], i2[4][2];
    #pragma unroll
    for (int am = 0; am < 4; ++am)
        #pragma unroll
        for (int h = 0; h < 2; ++h) {
            b1[am][h] = b2[am][h] = -3.4e38f;
            i1[am][h] = i2[am][h] = 0;
        }

    float wnv[4][2];

    auto load_chunk = [&](int g) {
        const int st = g % STAGES, cg = g & (NKC - 1), tg = g >> 4;
        const uint32_t dbase = sb + (uint32_t)st * STAGE_BYTES + (uint32_t)larr * TILE_BYTES;
        const __nv_bfloat16* s0 = srcbase + (size_t)(isA ? row0 : tg * BN) * D_DIM + cg * KC;
        #pragma unroll
        for (int it = 0; it < 8; ++it) {
            int seg = it * 64 + lthr;
            int r = seg >> 2, j = seg & 3;
            uint32_t dst = dbase + (uint32_t)(r * PITCH_B + j * 16);
            const void* src = s0 + (size_t)r * D_DIM + j * 8;
            CP_ASYNC16(dst, src);
        }
    };

    auto load_wn = [&](int t) {
        #pragma unroll
        for (int an = 0; an < 4; ++an)
            #pragma unroll
            for (int p = 0; p < 2; ++p)
                wnv[an][p] = 0.5f * __ldg(&g_wnorm[t * BN + wn * 32 + an * 8 + (lane & 3) * 2 + p]);
    };

    // prologue
    load_chunk(0); CP_COMMIT();
    load_chunk(1); CP_COMMIT();
    load_wn(0);

    int tile = 0;
    const int TOTAL = NTILE * NKC;
    for (int g = 0; g < TOTAL; ++g) {
        CP_WAIT(1);
        __syncthreads();
        if (g + 2 < TOTAL) load_chunk(g + 2);
        CP_COMMIT();

        const uint32_t base = sb + (uint32_t)(g % STAGES) * STAGE_BYTES;
        #pragma unroll
        for (int ks = 0; ks < 2; ++ks) {
            uint32_t ah[4][4], al[4][4], bh[2][4], bl[2][4];
            #pragma unroll
            for (int am = 0; am < 4; ++am) {
                uint32_t ad = base + a_base_row + (uint32_t)(am * 16 * PITCH_B) + lm_off + ks * 32;
                ldsm4(ah[am], ad);
                ldsm4(al[am], ad + TILE_BYTES);
            }
            #pragma unroll
            for (int bp = 0; bp < 2; ++bp) {
                uint32_t bd = base + 2 * TILE_BYTES + b_base_row + (uint32_t)(bp * 16 * PITCH_B) + lm_off + ks * 32;
                ldsm4(bh[bp], bd);
                ldsm4(bl[bp], bd + TILE_BYTES);
            }
            // term 1: hi*hi
            #pragma unroll
            for (int am = 0; am < 4; ++am)
                #pragma unroll
                for (int an = 0; an < 4; ++an)
                    mma16816(acc[am][an], ah[am], bh[an >> 1][an & 1], bh[an >> 1][(an & 1) + 2]);
            // term 2: hi*lo
            #pragma unroll
            for (int am = 0; am < 4; ++am)
                #pragma unroll
                for (int an = 0; an < 4; ++an)
                    mma16816(acc[am][an], ah[am], bl[an >> 1][an & 1], bl[an >> 1][(an & 1) + 2]);
            // term 3: lo*hi
            #pragma unroll
            for (int am = 0; am < 4; ++am)
                #pragma unroll
                for (int an = 0; an < 4; ++an)
                    mma16816(acc[am][an], al[am], bh[an >> 1][an & 1], bh[an >> 1][(an & 1) + 2]);
        }

        if ((g & (NKC - 1)) == (NKC - 1)) {
            // epilogue: score = dot - 0.5*||w||^2, running top-2
            #pragma unroll
            for (int am = 0; am < 4; ++am)
                #pragma unroll
                for (int an = 0; an < 4; ++an)
                    #pragma unroll
                    for (int j = 0; j < 4; ++j) {
                        int h = j >> 1, p = j & 1;
                        float m = acc[am][an][j] - wnv[an][p];
                        int col = tile * BN + wn * 32 + an * 8 + (lane & 3) * 2 + p;
                        if (m > b1[am][h]) {
                            b2[am][h] = b1[am][h]; i2[am][h] = i1[am][h];
                            b1[am][h] = m;         i1[am][h] = col;
                        } else if (m > b2[am][h]) {
                            b2[am][h] = m;         i2[am][h] = col;
                        }
                        acc[am][an][j] = 0.f;
                    }
            ++tile;
            if (tile < NTILE) load_wn(tile);
        }
    }

    CP_WAIT(0);
    __syncthreads();

    // cross-thread top-2 reduction: 16 slots per row
    float* rb1 = reinterpret_cast<float*>(smem);
    float* rb2 = rb1 + BM * 16;
    int*   ri1 = reinterpret_cast<int*>(rb2 + BM * 16);
    int*   ri2 = ri1 + BM * 16;
    #pragma unroll
    for (int am = 0; am < 4; ++am)
        #pragma unroll
        for (int h = 0; h < 2; ++h) {
            int rl = wm * 64 + am * 16 + h * 8 + (lane >> 2);
            int slot = wn * 4 + (lane & 3);
            rb1[rl * 16 + slot] = b1[am][h];
            rb2[rl * 16 + slot] = b2[am][h];
            ri1[rl * 16 + slot] = i1[am][h];
            ri2[rl * 16 + slot] = i2[am][h];
        }
    __syncthreads();
    if (tid < BM) {
        float B1 = -3.4e38f, B2 = -3.4e38f;
        int   I1 = 0, I2 = 0;
        #pragma unroll
        for (int s = 0; s < 16; ++s) {
            #pragma unroll
            for (int q = 0; q < 2; ++q) {
                float v = q ? rb2[tid * 16 + s] : rb1[tid * 16 + s];
                int   ii = q ? ri2[tid * 16 + s] : ri1[tid * 16 + s];
                if (v > B1 || (v == B1 && ii < I1)) {
                    B2 = B1; I2 = I1; B1 = v; I1 = ii;
                } else if (v > B2 || (v == B2 && ii < I2)) {
                    B2 = v; I2 = ii;
                }
            }
        }
        g_cand[row0 + tid] = make_int2(I1, I2);
    }
}

// ============================================================
// fixup: exact fp64 rescoring of the 2 candidates per row
// one warp per row; d(k) = sum_d w*(w - 2x)   (||x||^2 dropped)
// ============================================================
__global__ void fixup_kernel(const float* __restrict__ X,
                             const float* __restrict__ W) {
    int row = blockIdx.x * 8 + (threadIdx.x >> 5);
    int lane = threadIdx.x & 31;
    int2 cd = g_cand[row];
    const float* xr = X + (size_t)row * D_DIM;

    double d[2];
    #pragma unroll
    for (int c = 0; c < 2; ++c) {
        int k = c ? cd.y : cd.x;
        const float* wr = W + (size_t)k * D_DIM;
        double s = 0.0;
        #pragma unroll
        for (int j = 0; j < 4; ++j) {
            int dd = lane * 4 + j * 128;
            float4 w4 = *reinterpret_cast<const float4*>(wr + dd);
            float4 x4 = *reinterpret_cast<const float4*>(xr + dd);
            s += (double)w4.x * ((double)w4.x - 2.0 * (double)x4.x);
            s += (double)w4.y * ((double)w4.y - 2.0 * (double)x4.y);
            s += (double)w4.z * ((double)w4.z - 2.0 * (double)x4.z);
            s += (double)w4.w * ((double)w4.w - 2.0 * (double)x4.w);
        }
        #pragma unroll
        for (int o = 16; o > 0; o >>= 1)
            s += __shfl_xor_sync(0xffffffffu, s, o);
        d[c] = s;
    }
    if (lane == 0) {
        int k;
        if (d[1] < d[0] || (d[1] == d[0] && cd.y < cd.x)) k = cd.y; else k = cd.x;
        g_idx[row] = k;
    }
}

// ============================================================
// gather + loss
// ============================================================
__global__ void gather_kernel(const float* __restrict__ X,
                              const float* __restrict__ W,
                              float* __restrict__ out) {
    int n = blockIdx.x;
    int k = g_idx[n];
    const float* wr = W + (size_t)k * D_DIM;
    const float* xr = X + (size_t)n * D_DIM;
    float* orow = out + (size_t)n * D_DIM;

    int d = threadIdx.x * 4;
    float4 q  = *reinterpret_cast<const float4*>(wr + d);
    float4 xv = *reinterpret_cast<const float4*>(xr + d);
    *reinterpret_cast<float4*>(orow + d) = q;
    float dx = q.x - xv.x, dy = q.y - xv.y, dz = q.z - xv.z, dw = q.w - xv.w;
    float s = dx * dx + dy * dy + dz * dz + dw * dw;

    #pragma unroll
    for (int o = 16; o > 0; o >>= 1) s += __shfl_xor_sync(0xffffffffu, s, o);
    __shared__ float sm[4];
    if ((threadIdx.x & 31) == 0) sm[threadIdx.x >> 5] = s;
    __syncthreads();
    if (threadIdx.x == 0) atomicAdd(&g_loss, sm[0] + sm[1] + sm[2] + sm[3]);
}

__global__ void loss_kernel(float* __restrict__ out, int pos) {
    out[pos] = 1.25f * g_loss / (float)(N_ROWS * D_DIM);
}

// ============================================================
extern "C" void kernel_launch(void* const* d_in, const int* in_sizes, int n_in,
                              void* d_out, int out_size) {
    const float* x = (const float*)d_in[0];
    const float* W = (const float*)d_in[1];
    if (in_sizes[0] == K_CODES * D_DIM && in_sizes[1] == N_ROWS * D_DIM) {
        const float* t = x; x = W; W = t;
    }
    float* out = (float*)d_out;

    cudaFuncSetAttribute(argmin_mma, cudaFuncAttributeMaxDynamicSharedMemorySize, SMEM_DYN);

    split_x_kernel<<<(N_ROWS * D_DIM / 4) / 256, 256>>>(x);
    split_w_kernel<<<(K_CODES * D_DIM / 4) / 256, 256>>>(W);
    wnorm_kernel  <<<K_CODES, 128>>>(W);
    argmin_mma    <<<N_ROWS / BM, 256, SMEM_DYN>>>();
    fixup_kernel  <<<N_ROWS / 8, 256>>>(x, W);
    gather_kernel <<<N_ROWS, 128>>>(x, W, out);
    loss_kernel   <<<1, 1>>>(out, out_size - 1);
}

// round 8
// speedup vs baseline: 3.5621x; 1.0701x over previous
#include <cuda_runtime.h>
#include <cuda_bf16.h>
#include <cstdint>

#define N_ROWS  16384
#define D_DIM   512
#define K_CODES 8192

#define BM 128
#define BN 128
#define KC 32            // depth per chunk
#define NKC 16           // 512/32
#define NTILE 64         // 8192/128
#define STAGES 3
#define PITCH_B 80       // bytes per smem row (40 bf16, conflict-free for ldmatrix)
#define TILE_BYTES 10240 // 128 * 80
#define STAGE_BYTES 40960
#define SMEM_DYN (STAGES * STAGE_BYTES)

// ---------------- device scratch (static: no allocations) ----------------
__device__ __nv_bfloat16 g_xhi[N_ROWS * D_DIM];
__device__ __nv_bfloat16 g_xlo[N_ROWS * D_DIM];
__device__ __nv_bfloat16 g_whi[K_CODES * D_DIM];
__device__ __nv_bfloat16 g_wlo[K_CODES * D_DIM];
__device__ float g_wnorm[K_CODES];
__device__ int2  g_cand[N_ROWS];
__device__ int   g_idx[N_ROWS];
__device__ float g_loss;

// ---------------- helpers ----------------
__device__ __forceinline__ uint32_t smem_u32(const void* p) {
    uint32_t a;
    asm("{ .reg .u64 t; cvta.to.shared.u64 t, %1; cvt.u32.u64 %0, t; }" : "=r"(a) : "l"(p));
    return a;
}

__device__ __forceinline__ void split4(float4 v, uint32_t& h0, uint32_t& h1,
                                       uint32_t& l0, uint32_t& l1) {
    asm("cvt.rn.bf16x2.f32 %0, %1, %2;" : "=r"(h0) : "f"(v.y), "f"(v.x));
    asm("cvt.rn.bf16x2.f32 %0, %1, %2;" : "=r"(h1) : "f"(v.w), "f"(v.z));
    float hx = __uint_as_float(h0 << 16);
    float hy = __uint_as_float(h0 & 0xffff0000u);
    float hz = __uint_as_float(h1 << 16);
    float hw = __uint_as_float(h1 & 0xffff0000u);
    float lx = v.x - hx, ly = v.y - hy, lz = v.z - hz, lw = v.w - hw;
    asm("cvt.rn.bf16x2.f32 %0, %1, %2;" : "=r"(l0) : "f"(ly), "f"(lx));
    asm("cvt.rn.bf16x2.f32 %0, %1, %2;" : "=r"(l1) : "f"(lw), "f"(lz));
}

__device__ __forceinline__ void ldsm4(uint32_t* r, uint32_t addr) {
    asm volatile("ldmatrix.sync.aligned.m8n8.x4.shared.b16 {%0,%1,%2,%3}, [%4];"
                 : "=r"(r[0]), "=r"(r[1]), "=r"(r[2]), "=r"(r[3]) : "r"(addr));
}

__device__ __forceinline__ void mma16816(float* c, const uint32_t* a,
                                         uint32_t b0, uint32_t b1) {
    asm volatile(
        "mma.sync.aligned.m16n8k16.row.col.f32.bf16.bf16.f32 "
        "{%0,%1,%2,%3}, {%4,%5,%6,%7}, {%8,%9}, {%0,%1,%2,%3};"
        : "+f"(c[0]), "+f"(c[1]), "+f"(c[2]), "+f"(c[3])
        : "r"(a[0]), "r"(a[1]), "r"(a[2]), "r"(a[3]), "r"(b0), "r"(b1));
}

#define CP_ASYNC16(dst, src) \
    asm volatile("cp.async.cg.shared.global [%0], [%1], 16;" :: "r"(dst), "l"(src))
#define CP_COMMIT()   asm volatile("cp.async.commit_group;" ::: "memory")
#define CP_WAIT(n)    asm volatile("cp.async.wait_group %0;" :: "n"(n) : "memory")

// ============================================================
// split kernels: fp32 -> bf16 hi/lo planes
// ============================================================
__global__ void split_x_kernel(const float* __restrict__ src) {
    int i = blockIdx.x * blockDim.x + threadIdx.x;   // over float4s
    float4 v = reinterpret_cast<const float4*>(src)[i];
    uint32_t h0, h1, l0, l1;
    split4(v, h0, h1, l0, l1);
    reinterpret_cast<uint2*>(g_xhi)[i] = make_uint2(h0, h1);
    reinterpret_cast<uint2*>(g_xlo)[i] = make_uint2(l0, l1);
}
__global__ void split_w_kernel(const float* __restrict__ src) {
    int i = blockIdx.x * blockDim.x + threadIdx.x;
    float4 v = reinterpret_cast<const float4*>(src)[i];
    uint32_t h0, h1, l0, l1;
    split4(v, h0, h1, l0, l1);
    reinterpret_cast<uint2*>(g_whi)[i] = make_uint2(h0, h1);
    reinterpret_cast<uint2*>(g_wlo)[i] = make_uint2(l0, l1);
}

// ============================================================
// wnorm + zero loss
// ============================================================
__global__ void wnorm_kernel(const float* __restrict__ W) {
    int k = blockIdx.x;
    const float* row = W + (size_t)k * D_DIM;
    int d = threadIdx.x * 4;
    float4 v = *reinterpret_cast<const float4*>(row + d);
    float s = v.x * v.x + v.y * v.y + v.z * v.z + v.w * v.w;
    #pragma unroll
    for (int o = 16; o > 0; o >>= 1) s += __shfl_xor_sync(0xffffffffu, s, o);
    __shared__ float sm[4];
    if ((threadIdx.x & 31) == 0) sm[threadIdx.x >> 5] = s;
    __syncthreads();
    if (threadIdx.x == 0) {
        g_wnorm[k] = sm[0] + sm[1] + sm[2] + sm[3];
        if (k == 0) g_loss = 0.f;
    }
}

// ============================================================
// fused split-bf16 HMMA GEMM + top-2 argmax
// grid = 128 row tiles, 512 threads (16 warps, 4x4), warp tile 32x32
// ============================================================
__global__ void __launch_bounds__(512, 1)
argmin_mma() {
    extern __shared__ __align__(16) char smem[];
    const uint32_t sb = smem_u32(smem);
    const int tid  = threadIdx.x;
    const int lane = tid & 31;
    const int wid  = tid >> 5;
    const int wm = wid >> 2;          // 0..3 : 32-row slab
    const int wn = wid & 3;           // 0..3 : 32-col slab
    const int row0 = blockIdx.x * BM;

    // cp.async role: 4 arrays x 128 threads
    const int larr = tid >> 7;        // 0:Ahi 1:Alo 2:Bhi 3:Blo
    const int lthr = tid & 127;
    const bool isA = larr < 2;
    const __nv_bfloat16* srcbase =
        (larr == 0) ? g_xhi : (larr == 1) ? g_xlo : (larr == 2) ? g_whi : g_wlo;

    const uint32_t lm_off = (uint32_t)((lane & 15) * PITCH_B + (lane >> 4) * 16);
    const uint32_t a_base_row = (uint32_t)(wm * 32) * PITCH_B;
    const uint32_t b_base_row = (uint32_t)(wn * 32) * PITCH_B;

    float acc[2][4][4];
    #pragma unroll
    for (int am = 0; am < 2; ++am)
        #pragma unroll
        for (int an = 0; an < 4; ++an)
            #pragma unroll
            for (int j = 0; j < 4; ++j) acc[am][an][j] = 0.f;

    // per-thread top-2 per (am, h) row
    float b1[2][2], b2[2][2];
    int   i1[2][2], i2[2][2];
    #pragma unroll
    for (int am = 0; am < 2; ++am)
        #pragma unroll
        for (int h = 0; h < 2; ++h) {
            b1[am][h] = b2[am][h] = -3.4e38f;
            i1[am][h] = i2[am][h] = 0;
        }

    float wnv[4][2];

    auto load_chunk = [&](int g) {
        const int st = g % STAGES, cg = g & (NKC - 1), tg = g >> 4;
        const uint32_t dbase = sb + (uint32_t)st * STAGE_BYTES + (uint32_t)larr * TILE_BYTES;
        const __nv_bfloat16* s0 = srcbase + (size_t)(isA ? row0 : tg * BN) * D_DIM + cg * KC;
        #pragma unroll
        for (int it = 0; it < 4; ++it) {
            int seg = it * 128 + lthr;
            int r = seg >> 2, j = seg & 3;
            uint32_t dst = dbase + (uint32_t)(r * PITCH_B + j * 16);
            const void* src = s0 + (size_t)r * D_DIM + j * 8;
            CP_ASYNC16(dst, src);
        }
    };

    auto load_wn = [&](int t) {
        #pragma unroll
        for (int an = 0; an < 4; ++an)
            #pragma unroll
            for (int p = 0; p < 2; ++p)
                wnv[an][p] = 0.5f * __ldg(&g_wnorm[t * BN + wn * 32 + an * 8 + (lane & 3) * 2 + p]);
    };

    // prologue
    load_chunk(0); CP_COMMIT();
    load_chunk(1); CP_COMMIT();
    load_wn(0);

    int tile = 0;
    const int TOTAL = NTILE * NKC;
    for (int g = 0; g < TOTAL; ++g) {
        CP_WAIT(1);
        __syncthreads();
        if (g + 2 < TOTAL) load_chunk(g + 2);
        CP_COMMIT();

        const uint32_t base = sb + (uint32_t)(g % STAGES) * STAGE_BYTES;
        #pragma unroll
        for (int ks = 0; ks < 2; ++ks) {
            uint32_t ah[2][4], al[2][4], bh[2][4], bl[2][4];
            // hi A frags + hi B frags -> term 1
            #pragma unroll
            for (int am = 0; am < 2; ++am) {
                uint32_t ad = base + a_base_row + (uint32_t)(am * 16 * PITCH_B) + lm_off + ks * 32;
                ldsm4(ah[am], ad);
            }
            #pragma unroll
            for (int bp = 0; bp < 2; ++bp) {
                uint32_t bd = base + 2 * TILE_BYTES + b_base_row + (uint32_t)(bp * 16 * PITCH_B) + lm_off + ks * 32;
                ldsm4(bh[bp], bd);
            }
            #pragma unroll
            for (int am = 0; am < 2; ++am)
                #pragma unroll
                for (int an = 0; an < 4; ++an)
                    mma16816(acc[am][an], ah[am], bh[an >> 1][an & 1], bh[an >> 1][(an & 1) + 2]);
            // lo B frags -> term 2 (hi*lo)
            #pragma unroll
            for (int bp = 0; bp < 2; ++bp) {
                uint32_t bd = base + 3 * TILE_BYTES + b_base_row + (uint32_t)(bp * 16 * PITCH_B) + lm_off + ks * 32;
                ldsm4(bl[bp], bd);
            }
            #pragma unroll
            for (int am = 0; am < 2; ++am)
                #pragma unroll
                for (int an = 0; an < 4; ++an)
                    mma16816(acc[am][an], ah[am], bl[an >> 1][an & 1], bl[an >> 1][(an & 1) + 2]);
            // lo A frags -> term 3 (lo*hi)
            #pragma unroll
            for (int am = 0; am < 2; ++am) {
                uint32_t ad = base + TILE_BYTES + a_base_row + (uint32_t)(am * 16 * PITCH_B) + lm_off + ks * 32;
                ldsm4(al[am], ad);
            }
            #pragma unroll
            for (int am = 0; am < 2; ++am)
                #pragma unroll
                for (int an = 0; an < 4; ++an)
                    mma16816(acc[am][an], al[am], bh[an >> 1][an & 1], bh[an >> 1][(an & 1) + 2]);
        }

        if ((g & (NKC - 1)) == (NKC - 1)) {
            // epilogue: score = dot - 0.5*||w||^2, running top-2
            #pragma unroll
            for (int am = 0; am < 2; ++am)
                #pragma unroll
                for (int an = 0; an < 4; ++an)
                    #pragma unroll
                    for (int j = 0; j < 4; ++j) {
                        int h = j >> 1, p = j & 1;
                        float m = acc[am][an][j] - wnv[an][p];
                        int col = tile * BN + wn * 32 + an * 8 + (lane & 3) * 2 + p;
                        if (m > b1[am][h]) {
                            b2[am][h] = b1[am][h]; i2[am][h] = i1[am][h];
                            b1[am][h] = m;         i1[am][h] = col;
                        } else if (m > b2[am][h]) {
                            b2[am][h] = m;         i2[am][h] = col;
                        }
                        acc[am][an][j] = 0.f;
                    }
            ++tile;
            if (tile < NTILE) load_wn(tile);
        }
    }

    CP_WAIT(0);
    __syncthreads();

    // cross-thread top-2 reduction: 16 slots per row (4 wn-warps x 4 lane-cols)
    float* rb1 = reinterpret_cast<float*>(smem);
    float* rb2 = rb1 + BM * 16;
    int*   ri1 = reinterpret_cast<int*>(rb2 + BM * 16);
    int*   ri2 = ri1 + BM * 16;
    #pragma unroll
    for (int am = 0; am < 2; ++am)
        #pragma unroll
        for (int h = 0; h < 2; ++h) {
            int rl = wm * 32 + am * 16 + h * 8 + (lane >> 2);
            int slot = wn * 4 + (lane & 3);
            rb1[rl * 16 + slot] = b1[am][h];
            rb2[rl * 16 + slot] = b2[am][h];
            ri1[rl * 16 + slot] = i1[am][h];
            ri2[rl * 16 + slot] = i2[am][h];
        }
    __syncthreads();
    if (tid < BM) {
        float B1 = -3.4e38f, B2 = -3.4e38f;
        int   I1 = 0, I2 = 0;
        #pragma unroll
        for (int s = 0; s < 16; ++s) {
            #pragma unroll
            for (int q = 0; q < 2; ++q) {
                float v = q ? rb2[tid * 16 + s] : rb1[tid * 16 + s];
                int   ii = q ? ri2[tid * 16 + s] : ri1[tid * 16 + s];
                if (v > B1 || (v == B1 && ii < I1)) {
                    B2 = B1; I2 = I1; B1 = v; I1 = ii;
                } else if (v > B2 || (v == B2 && ii < I2)) {
                    B2 = v; I2 = ii;
                }
            }
        }
        g_cand[row0 + tid] = make_int2(I1, I2);
    }
}

// ============================================================
// fixup: exact fp64 rescoring of the 2 candidates per row
// one warp per row; d(k) = sum_d w*(w - 2x)   (||x||^2 dropped)
// ============================================================
__global__ void fixup_kernel(const float* __restrict__ X,
                             const float* __restrict__ W) {
    int row = blockIdx.x * 8 + (threadIdx.x >> 5);
    int lane = threadIdx.x & 31;
    int2 cd = g_cand[row];
    const float* xr = X + (size_t)row * D_DIM;

    double d[2];
    #pragma unroll
    for (int c = 0; c < 2; ++c) {
        int k = c ? cd.y : cd.x;
        const float* wr = W + (size_t)k * D_DIM;
        double s = 0.0;
        #pragma unroll
        for (int j = 0; j < 4; ++j) {
            int dd = lane * 4 + j * 128;
            float4 w4 = *reinterpret_cast<const float4*>(wr + dd);
            float4 x4 = *reinterpret_cast<const float4*>(xr + dd);
            s += (double)w4.x * ((double)w4.x - 2.0 * (double)x4.x);
            s += (double)w4.y * ((double)w4.y - 2.0 * (double)x4.y);
            s += (double)w4.z * ((double)w4.z - 2.0 * (double)x4.z);
            s += (double)w4.w * ((double)w4.w - 2.0 * (double)x4.w);
        }
        #pragma unroll
        for (int o = 16; o > 0; o >>= 1)
            s += __shfl_xor_sync(0xffffffffu, s, o);
        d[c] = s;
    }
    if (lane == 0) {
        int k;
        if (d[1] < d[0] || (d[1] == d[0] && cd.y < cd.x)) k = cd.y; else k = cd.x;
        g_idx[row] = k;
    }
}

// ============================================================
// gather + loss
// ============================================================
__global__ void gather_kernel(const float* __restrict__ X,
                              const float* __restrict__ W,
                              float* __restrict__ out) {
    int n = blockIdx.x;
    int k = g_idx[n];
    const float* wr = W + (size_t)k * D_DIM;
    const float* xr = X + (size_t)n * D_DIM;
    float* orow = out + (size_t)n * D_DIM;

    int d = threadIdx.x * 4;
    float4 q  = *reinterpret_cast<const float4*>(wr + d);
    float4 xv = *reinterpret_cast<const float4*>(xr + d);
    *reinterpret_cast<float4*>(orow + d) = q;
    float dx = q.x - xv.x, dy = q.y - xv.y, dz = q.z - xv.z, dw = q.w - xv.w;
    float s = dx * dx + dy * dy + dz * dz + dw * dw;

    #pragma unroll
    for (int o = 16; o > 0; o >>= 1) s += __shfl_xor_sync(0xffffffffu, s, o);
    __shared__ float sm[4];
    if ((threadIdx.x & 31) == 0) sm[threadIdx.x >> 5] = s;
    __syncthreads();
    if (threadIdx.x == 0) atomicAdd(&g_loss, sm[0] + sm[1] + sm[2] + sm[3]);
}

__global__ void loss_kernel(float* __restrict__ out, int pos) {
    out[pos] = 1.25f * g_loss / (float)(N_ROWS * D_DIM);
}

// ============================================================
extern "C" void kernel_launch(void* const* d_in, const int* in_sizes, int n_in,
                              void* d_out, int out_size) {
    const float* x = (const float*)d_in[0];
    const float* W = (const float*)d_in[1];
    if (in_sizes[0] == K_CODES * D_DIM && in_sizes[1] == N_ROWS * D_DIM) {
        const float* t = x; x = W; W = t;
    }
    float* out = (float*)d_out;

    cudaFuncSetAttribute(argmin_mma, cudaFuncAttributeMaxDynamicSharedMemorySize, SMEM_DYN);

    split_x_kernel<<<(N_ROWS * D_DIM / 4) / 256, 256>>>(x);
    split_w_kernel<<<(K_CODES * D_DIM / 4) / 256, 256>>>(W);
    wnorm_kernel  <<<K_CODES, 128>>>(W);
    argmin_mma    <<<N_ROWS / BM, 512, SMEM_DYN>>>();
    fixup_kernel  <<<N_ROWS / 8, 256>>>(x, W);
    gather_kernel <<<N_ROWS, 128>>>(x, W, out);
    loss_kernel   <<<1, 1>>>(out, out_size - 1);
}

// round 10
// speedup vs baseline: 4.7088x; 1.3219x over previous
#include <cuda_runtime.h>
#include <cuda_fp16.h>
#include <cstdint>

#define N_ROWS  16384
#define D_DIM   512
#define K_CODES 8192

#define BM 128
#define BN 128
#define KC 64            // depth per chunk
#define NKC 8            // 512/64
#define NTILE 64         // 8192/128
#define STAGES 3
#define PITCH_B 144      // 128 data bytes + 16 pad (conflict-free ldmatrix)
#define PLANE_BYTES (128 * PITCH_B)          // 18432
#define STAGE_BYTES (3 * PLANE_BYTES)        // 55296
#define SMEM_DYN (STAGES * STAGE_BYTES)      // 165888

// ---------------- device scratch (static: no allocations) ----------------
__device__ __half g_xh[N_ROWS * D_DIM];
__device__ __half g_wh[K_CODES * D_DIM];
__device__ __half g_wl[K_CODES * D_DIM];
__device__ float g_wnorm[K_CODES];
__device__ int4  g_cand[N_ROWS];
__device__ int   g_idx[N_ROWS];
__device__ float g_loss;

// ---------------- helpers ----------------
__device__ __forceinline__ uint32_t smem_u32(const void* p) {
    uint32_t a;
    asm("{ .reg .u64 t; cvta.to.shared.u64 t, %1; cvt.u32.u64 %0, t; }" : "=r"(a) : "l"(p));
    return a;
}

__device__ __forceinline__ void ldsm4(uint32_t* r, uint32_t addr) {
    asm volatile("ldmatrix.sync.aligned.m8n8.x4.shared.b16 {%0,%1,%2,%3}, [%4];"
                 : "=r"(r[0]), "=r"(r[1]), "=r"(r[2]), "=r"(r[3]) : "r"(addr));
}

__device__ __forceinline__ void mma16816(float* c, const uint32_t* a,
                                         uint32_t b0, uint32_t b1) {
    asm volatile(
        "mma.sync.aligned.m16n8k16.row.col.f32.f16.f16.f32 "
        "{%0,%1,%2,%3}, {%4,%5,%6,%7}, {%8,%9}, {%0,%1,%2,%3};"
        : "+f"(c[0]), "+f"(c[1]), "+f"(c[2]), "+f"(c[3])
        : "r"(a[0]), "r"(a[1]), "r"(a[2]), "r"(a[3]), "r"(b0), "r"(b1));
}

#define CP_ASYNC16(dst, src) \
    asm volatile("cp.async.cg.shared.global [%0], [%1], 16;" :: "r"(dst), "l"(src))
#define CP_COMMIT()   asm volatile("cp.async.commit_group;" ::: "memory")
#define CP_WAIT(n)    asm volatile("cp.async.wait_group %0;" :: "n"(n) : "memory")

// ============================================================
// split kernels: fp32 -> fp16 (X: hi only; W: hi + lo)
// ============================================================
__global__ void split_x_kernel(const float* __restrict__ src) {
    int i = blockIdx.x * blockDim.x + threadIdx.x;   // over float4s
    float4 v = reinterpret_cast<const float4*>(src)[i];
    __half2 h01 = __floats2half2_rn(v.x, v.y);
    __half2 h23 = __floats2half2_rn(v.z, v.w);
    reinterpret_cast<__half2*>(g_xh)[i * 2]     = h01;
    reinterpret_cast<__half2*>(g_xh)[i * 2 + 1] = h23;
}
__global__ void split_w_kernel(const float* __restrict__ src) {
    int i = blockIdx.x * blockDim.x + threadIdx.x;
    float4 v = reinterpret_cast<const float4*>(src)[i];
    __half2 h01 = __floats2half2_rn(v.x, v.y);
    __half2 h23 = __floats2half2_rn(v.z, v.w);
    float lx = v.x - __half2float(__low2half(h01));
    float ly = v.y - __half2float(__high2half(h01));
    float lz = v.z - __half2float(__low2half(h23));
    float lw = v.w - __half2float(__high2half(h23));
    reinterpret_cast<__half2*>(g_wh)[i * 2]     = h01;
    reinterpret_cast<__half2*>(g_wh)[i * 2 + 1] = h23;
    reinterpret_cast<__half2*>(g_wl)[i * 2]     = __floats2half2_rn(lx, ly);
    reinterpret_cast<__half2*>(g_wl)[i * 2 + 1] = __floats2half2_rn(lz, lw);
}

// ============================================================
// wnorm + zero loss
// ============================================================
__global__ void wnorm_kernel(const float* __restrict__ W) {
    int k = blockIdx.x;
    const float* row = W + (size_t)k * D_DIM;
    int d = threadIdx.x * 4;
    float4 v = *reinterpret_cast<const float4*>(row + d);
    float s = v.x * v.x + v.y * v.y + v.z * v.z + v.w * v.w;
    #pragma unroll
    for (int o = 16; o > 0; o >>= 1) s += __shfl_xor_sync(0xffffffffu, s, o);
    __shared__ float sm[4];
    if ((threadIdx.x & 31) == 0) sm[threadIdx.x >> 5] = s;
    __syncthreads();
    if (threadIdx.x == 0) {
        g_wnorm[k] = sm[0] + sm[1] + sm[2] + sm[3];
        if (k == 0) g_loss = 0.f;
    }
}

// ============================================================
// fused fp16 2-term HMMA GEMM + top-2 argmax (top-4 global)
// grid = 128 row tiles, 512 threads (16 warps, 4x4), warp tile 32x32
// ============================================================
__global__ void __launch_bounds__(512, 1)
argmin_mma() {
    extern __shared__ __align__(16) char smem[];
    const uint32_t sb = smem_u32(smem);
    const int tid  = threadIdx.x;
    const int lane = tid & 31;
    const int wid  = tid >> 5;
    const int wm = wid >> 2;          // 0..3 : 32-row slab
    const int wn = wid & 3;           // 0..3 : 32-col slab
    const int row0 = blockIdx.x * BM;

    const uint32_t lm_off = (uint32_t)((lane & 15) * PITCH_B + (lane >> 4) * 16);
    const uint32_t a_base_row = (uint32_t)(wm * 32) * PITCH_B;
    const uint32_t b_base_row = (uint32_t)(wn * 32) * PITCH_B;

    float acc[2][4][4];
    #pragma unroll
    for (int am = 0; am < 2; ++am)
        #pragma unroll
        for (int an = 0; an < 4; ++an)
            #pragma unroll
            for (int j = 0; j < 4; ++j) acc[am][an][j] = 0.f;

    // per-thread top-2 per (am, h) row
    float b1[2][2], b2[2][2];
    int   i1[2][2], i2[2][2];
    #pragma unroll
    for (int am = 0; am < 2; ++am)
        #pragma unroll
        for (int h = 0; h < 2; ++h) {
            b1[am][h] = b2[am][h] = -3.4e38f;
            i1[am][h] = i2[am][h] = 0;
        }

    float wnv[4][2];

    // 3 planes per stage: 0=A-hi (this CTA's X rows), 1=W-hi, 2=W-lo.
    // 3 planes x 128 rows x 8 segs = 3072 cp.async16 / 512 thr = 6 each.
    auto load_chunk = [&](int g) {
        const int st = g % STAGES, cg = g & (NKC - 1), tg = g >> 3;
        const uint32_t dbase = sb + (uint32_t)st * STAGE_BYTES;
        #pragma unroll
        for (int it = 0; it < 6; ++it) {
            int v = it * 512 + tid;
            int p = v >> 10;          // plane
            int rem = v & 1023;
            int r = rem >> 3, j = rem & 7;
            const __half* s0 =
                (p == 0 ? g_xh + (size_t)(row0 + r) * D_DIM
                        : (p == 1 ? g_wh : g_wl) + (size_t)(tg * BN + r) * D_DIM)
                + cg * KC + j * 8;
            uint32_t dst = dbase + (uint32_t)(p * PLANE_BYTES + r * PITCH_B + j * 16);
            CP_ASYNC16(dst, s0);
        }
    };

    auto load_wn = [&](int t) {
        #pragma unroll
        for (int an = 0; an < 4; ++an)
            #pragma unroll
            for (int p = 0; p < 2; ++p)
                wnv[an][p] = 0.5f * __ldg(&g_wnorm[t * BN + wn * 32 + an * 8 + (lane & 3) * 2 + p]);
    };

    // prologue
    load_chunk(0); CP_COMMIT();
    load_chunk(1); CP_COMMIT();
    load_wn(0);

    int tile = 0;
    const int TOTAL = NTILE * NKC;   // 512
    for (int g = 0; g < TOTAL; ++g) {
        CP_WAIT(1);
        __syncthreads();
        if (g + 2 < TOTAL) load_chunk(g + 2);
        CP_COMMIT();

        const uint32_t base = sb + (uint32_t)(g % STAGES) * STAGE_BYTES;
        #pragma unroll
        for (int ks = 0; ks < 4; ++ks) {
            uint32_t ah[2][4], bh[2][4], bl[2][4];
            #pragma unroll
            for (int am = 0; am < 2; ++am) {
                uint32_t ad = base + a_base_row + (uint32_t)(am * 16 * PITCH_B) + lm_off + ks * 32;
                ldsm4(ah[am], ad);
            }
            #pragma unroll
            for (int bp = 0; bp < 2; ++bp) {
                uint32_t bd = base + PLANE_BYTES + b_base_row + (uint32_t)(bp * 16 * PITCH_B) + lm_off + ks * 32;
                ldsm4(bh[bp], bd);
            }
            // term 1: xhi * whi
            #pragma unroll
            for (int am = 0; am < 2; ++am)
                #pragma unroll
                for (int an = 0; an < 4; ++an)
                    mma16816(acc[am][an], ah[am], bh[an >> 1][an & 1], bh[an >> 1][(an & 1) + 2]);
            // term 2: xhi * wlo
            #pragma unroll
            for (int bp = 0; bp < 2; ++bp) {
                uint32_t bd = base + 2 * PLANE_BYTES + b_base_row + (uint32_t)(bp * 16 * PITCH_B) + lm_off + ks * 32;
                ldsm4(bl[bp], bd);
            }
            #pragma unroll
            for (int am = 0; am < 2; ++am)
                #pragma unroll
                for (int an = 0; an < 4; ++an)
                    mma16816(acc[am][an], ah[am], bl[an >> 1][an & 1], bl[an >> 1][(an & 1) + 2]);
        }

        if ((g & (NKC - 1)) == (NKC - 1)) {
            // epilogue: score = dot - 0.5*||w||^2, running top-2
            #pragma unroll
            for (int am = 0; am < 2; ++am)
                #pragma unroll
                for (int an = 0; an < 4; ++an)
                    #pragma unroll
                    for (int j = 0; j < 4; ++j) {
                        int h = j >> 1, p = j & 1;
                        float m = acc[am][an][j] - wnv[an][p];
                        int col = tile * BN + wn * 32 + an * 8 + (lane & 3) * 2 + p;
                        if (m > b1[am][h]) {
                            b2[am][h] = b1[am][h]; i2[am][h] = i1[am][h];
                            b1[am][h] = m;         i1[am][h] = col;
                        } else if (m > b2[am][h]) {
                            b2[am][h] = m;         i2[am][h] = col;
                        }
                        acc[am][an][j] = 0.f;
                    }
            ++tile;
            if (tile < NTILE) load_wn(tile);
        }
    }

    CP_WAIT(0);
    __syncthreads();

    // cross-thread reduction to global top-4: 16 slots x 2 candidates per row
    float* rb1 = reinterpret_cast<float*>(smem);
    float* rb2 = rb1 + BM * 16;
    int*   ri1 = reinterpret_cast<int*>(rb2 + BM * 16);
    int*   ri2 = ri1 + BM * 16;
    #pragma unroll
    for (int am = 0; am < 2; ++am)
        #pragma unroll
        for (int h = 0; h < 2; ++h) {
            int rl = wm * 32 + am * 16 + h * 8 + (lane >> 2);
            int slot = wn * 4 + (lane & 3);
            rb1[rl * 16 + slot] = b1[am][h];
            rb2[rl * 16 + slot] = b2[am][h];
            ri1[rl * 16 + slot] = i1[am][h];
            ri2[rl * 16 + slot] = i2[am][h];
        }
    __syncthreads();
    if (tid < BM) {
        float B[4] = {-3.4e38f, -3.4e38f, -3.4e38f, -3.4e38f};
        int   I[4] = {0, 0, 0, 0};
        #pragma unroll
        for (int s = 0; s < 16; ++s) {
            #pragma unroll
            for (int q = 0; q < 2; ++q) {
                float v = q ? rb2[tid * 16 + s] : rb1[tid * 16 + s];
                int   ii = q ? ri2[tid * 16 + s] : ri1[tid * 16 + s];
                #pragma unroll
                for (int r = 0; r < 4; ++r) {
                    if (v > B[r] || (v == B[r] && ii < I[r])) {
                        // insert at r, shift down
                        #pragma unroll
                        for (int q2 = 3; q2 > r; --q2) { B[q2] = B[q2 - 1]; I[q2] = I[q2 - 1]; }
                        B[r] = v; I[r] = ii;
                        break;
                    }
                }
            }
        }
        g_cand[row0 + tid] = make_int4(I[0], I[1], I[2], I[3]);
    }
}

// ============================================================
// fixup: exact fp64 rescoring of the 4 candidates per row
// one warp per row; d(k) = sum_d w*(w - 2x)   (||x||^2 dropped)
// ============================================================
__global__ void fixup_kernel(const float* __restrict__ X,
                             const float* __restrict__ W) {
    int row = blockIdx.x * 8 + (threadIdx.x >> 5);
    int lane = threadIdx.x & 31;
    int4 cd = g_cand[row];
    int cand[4] = {cd.x, cd.y, cd.z, cd.w};
    const float* xr = X + (size_t)row * D_DIM;

    double bd = 1e300;
    int bk = 0x7fffffff;
    #pragma unroll
    for (int c = 0; c < 4; ++c) {
        int k = cand[c];
        const float* wr = W + (size_t)k * D_DIM;
        double s = 0.0;
        #pragma unroll
        for (int j = 0; j < 4; ++j) {
            int dd = lane * 4 + j * 128;
            float4 w4 = *reinterpret_cast<const float4*>(wr + dd);
            float4 x4 = *reinterpret_cast<const float4*>(xr + dd);
            s += (double)w4.x * ((double)w4.x - 2.0 * (double)x4.x);
            s += (double)w4.y * ((double)w4.y - 2.0 * (double)x4.y);
            s += (double)w4.z * ((double)w4.z - 2.0 * (double)x4.z);
            s += (double)w4.w * ((double)w4.w - 2.0 * (double)x4.w);
        }
        #pragma unroll
        for (int o = 16; o > 0; o >>= 1)
            s += __shfl_xor_sync(0xffffffffu, s, o);
        if (s < bd || (s == bd && k < bk)) { bd = s; bk = k; }
    }
    if (lane == 0) g_idx[row] = bk;
}

// ============================================================
// gather + loss
// ============================================================
__global__ void gather_kernel(const float* __restrict__ X,
                              const float* __restrict__ W,
                              float* __restrict__ out) {
    int n = blockIdx.x;
    int k = g_idx[n];
    const float* wr = W + (size_t)k * D_DIM;
    const float* xr = X + (size_t)n * D_DIM;
    float* orow = out + (size_t)n * D_DIM;

    int d = threadIdx.x * 4;
    float4 q  = *reinterpret_cast<const float4*>(wr + d);
    float4 xv = *reinterpret_cast<const float4*>(xr + d);
    *reinterpret_cast<float4*>(orow + d) = q;
    float dx = q.x - xv.x, dy = q.y - xv.y, dz = q.z - xv.z, dw = q.w - xv.w;
    float s = dx * dx + dy * dy + dz * dz + dw * dw;

    #pragma unroll
    for (int o = 16; o > 0; o >>= 1) s += __shfl_xor_sync(0xffffffffu, s, o);
    __shared__ float sm[4];
    if ((threadIdx.x & 31) == 0) sm[threadIdx.x >> 5] = s;
    __syncthreads();
    if (threadIdx.x == 0) atomicAdd(&g_loss, sm[0] + sm[1] + sm[2] + sm[3]);
}

__global__ void loss_kernel(float* __restrict__ out, int pos) {
    out[pos] = 1.25f * g_loss / (float)(N_ROWS * D_DIM);
}

// ============================================================
extern "C" void kernel_launch(void* const* d_in, const int* in_sizes, int n_in,
                              void* d_out, int out_size) {
    const float* x = (const float*)d_in[0];
    const float* W = (const float*)d_in[1];
    if (in_sizes[0] == K_CODES * D_DIM && in_sizes[1] == N_ROWS * D_DIM) {
        const float* t = x; x = W; W = t;
    }
    float* out = (float*)d_out;

    cudaFuncSetAttribute(argmin_mma, cudaFuncAttributeMaxDynamicSharedMemorySize, SMEM_DYN);

    split_x_kernel<<<(N_ROWS * D_DIM / 4) / 256, 256>>>(x);
    split_w_kernel<<<(K_CODES * D_DIM / 4) / 256, 256>>>(W);
    wnorm_kernel  <<<K_CODES, 128>>>(W);
    argmin_mma    <<<N_ROWS / BM, 512, SMEM_DYN>>>();
    fixup_kernel  <<<N_ROWS / 8, 256>>>(x, W);
    gather_kernel <<<N_ROWS, 128>>>(x, W, out);
    loss_kernel   <<<1, 1>>>(out, out_size - 1);
}

// round 11
// speedup vs baseline: 6.9976x; 1.4861x over previous
#include <cuda_runtime.h>
#include <cuda_fp16.h>
#include <cstdint>

#define N_ROWS  16384
#define D_DIM   512
#define K_CODES 8192

#define BM 128
#define BN 128
#define KC 128           // depth per chunk
#define NKC 4            // 512/128
#define NTILE 64         // 8192/128
#define STAGES 3
#define PITCH_B 272      // 256 data bytes + 16 pad (conflict-free ldmatrix)
#define PLANE_BYTES (128 * PITCH_B)          // 34816
#define STAGE_BYTES (2 * PLANE_BYTES)        // 69632 (A plane + B plane)
#define SMEM_DYN (STAGES * STAGE_BYTES)      // 208896

// ---------------- device scratch (static: no allocations) ----------------
__device__ __half g_xh[N_ROWS * D_DIM];
__device__ __half g_wh[K_CODES * D_DIM];
__device__ float g_wnorm[K_CODES];
__device__ int4  g_cand[N_ROWS];
__device__ float g_loss;

// ---------------- helpers ----------------
__device__ __forceinline__ uint32_t smem_u32(const void* p) {
    uint32_t a;
    asm("{ .reg .u64 t; cvta.to.shared.u64 t, %1; cvt.u32.u64 %0, t; }" : "=r"(a) : "l"(p));
    return a;
}

__device__ __forceinline__ void ldsm4(uint32_t* r, uint32_t addr) {
    asm volatile("ldmatrix.sync.aligned.m8n8.x4.shared.b16 {%0,%1,%2,%3}, [%4];"
                 : "=r"(r[0]), "=r"(r[1]), "=r"(r[2]), "=r"(r[3]) : "r"(addr));
}

__device__ __forceinline__ void mma16816(float* c, const uint32_t* a,
                                         uint32_t b0, uint32_t b1) {
    asm volatile(
        "mma.sync.aligned.m16n8k16.row.col.f32.f16.f16.f32 "
        "{%0,%1,%2,%3}, {%4,%5,%6,%7}, {%8,%9}, {%0,%1,%2,%3};"
        : "+f"(c[0]), "+f"(c[1]), "+f"(c[2]), "+f"(c[3])
        : "r"(a[0]), "r"(a[1]), "r"(a[2]), "r"(a[3]), "r"(b0), "r"(b1));
}

#define CP_ASYNC16(dst, src) \
    asm volatile("cp.async.cg.shared.global [%0], [%1], 16;" :: "r"(dst), "l"(src))
#define CP_COMMIT()   asm volatile("cp.async.commit_group;" ::: "memory")
#define CP_WAIT(n)    asm volatile("cp.async.wait_group %0;" :: "n"(n) : "memory")

// ============================================================
// convert X -> fp16
// ============================================================
__global__ void split_x_kernel(const float* __restrict__ src) {
    int i = blockIdx.x * blockDim.x + threadIdx.x;   // over float4s
    float4 v = reinterpret_cast<const float4*>(src)[i];
    reinterpret_cast<__half2*>(g_xh)[i * 2]     = __floats2half2_rn(v.x, v.y);
    reinterpret_cast<__half2*>(g_xh)[i * 2 + 1] = __floats2half2_rn(v.z, v.w);
}

// ============================================================
// convert W -> fp16, compute ||w||^2, zero loss  (one pass over W)
// one block per code row, 128 threads
// ============================================================
__global__ void split_wnorm_kernel(const float* __restrict__ W) {
    int k = blockIdx.x;
    const float* row = W + (size_t)k * D_DIM;
    int d = threadIdx.x * 4;
    float4 v = *reinterpret_cast<const float4*>(row + d);
    __half2* dst = reinterpret_cast<__half2*>(g_wh + (size_t)k * D_DIM + d);
    dst[0] = __floats2half2_rn(v.x, v.y);
    dst[1] = __floats2half2_rn(v.z, v.w);
    float s = v.x * v.x + v.y * v.y + v.z * v.z + v.w * v.w;
    #pragma unroll
    for (int o = 16; o > 0; o >>= 1) s += __shfl_xor_sync(0xffffffffu, s, o);
    __shared__ float sm[4];
    if ((threadIdx.x & 31) == 0) sm[threadIdx.x >> 5] = s;
    __syncthreads();
    if (threadIdx.x == 0) {
        g_wnorm[k] = sm[0] + sm[1] + sm[2] + sm[3];
        if (k == 0) g_loss = 0.f;
    }
}

// ============================================================
// fused fp16 HMMA GEMM + top-4 argmax candidates
// grid = 128 row tiles, 512 threads (16 warps, 4x4), warp tile 32x32
// ============================================================
__global__ void __launch_bounds__(512, 1)
argmin_mma() {
    extern __shared__ __align__(16) char smem[];
    const uint32_t sb = smem_u32(smem);
    const int tid  = threadIdx.x;
    const int lane = tid & 31;
    const int wid  = tid >> 5;
    const int wm = wid >> 2;          // 0..3 : 32-row slab
    const int wn = wid & 3;           // 0..3 : 32-col slab
    const int row0 = blockIdx.x * BM;

    const uint32_t lm_off = (uint32_t)((lane & 15) * PITCH_B + (lane >> 4) * 16);
    const uint32_t a_base_row = (uint32_t)(wm * 32) * PITCH_B;
    const uint32_t b_base_row = (uint32_t)(wn * 32) * PITCH_B;

    float acc[2][4][4];
    #pragma unroll
    for (int am = 0; am < 2; ++am)
        #pragma unroll
        for (int an = 0; an < 4; ++an)
            #pragma unroll
            for (int j = 0; j < 4; ++j) acc[am][an][j] = 0.f;

    // per-thread top-2 per (am, h) row
    float b1[2][2], b2[2][2];
    int   i1[2][2], i2[2][2];
    #pragma unroll
    for (int am = 0; am < 2; ++am)
        #pragma unroll
        for (int h = 0; h < 2; ++h) {
            b1[am][h] = b2[am][h] = -3.4e38f;
            i1[am][h] = i2[am][h] = 0;
        }

    float wnv[4][2];

    // 2 planes per stage: 0 = A (this CTA's X rows), 1 = W.
    // 2 planes x 128 rows x 16 segs = 4096 cp.async16 / 512 thr = 8 each.
    auto load_chunk = [&](int g) {
        const int st = g % STAGES, cg = g & (NKC - 1), tg = g >> 2;
        const uint32_t dbase = sb + (uint32_t)st * STAGE_BYTES;
        #pragma unroll
        for (int it = 0; it < 8; ++it) {
            int v = it * 512 + tid;
            int p = v >> 11;          // plane (0..1)
            int rem = v & 2047;
            int r = rem >> 4, j = rem & 15;
            const __half* s0 =
                (p == 0 ? g_xh + (size_t)(row0 + r) * D_DIM
                        : g_wh + (size_t)(tg * BN + r) * D_DIM)
                + cg * KC + j * 8;
            uint32_t dst = dbase + (uint32_t)(p * PLANE_BYTES + r * PITCH_B + j * 16);
            CP_ASYNC16(dst, s0);
        }
    };

    auto load_wn = [&](int t) {
        #pragma unroll
        for (int an = 0; an < 4; ++an)
            #pragma unroll
            for (int p = 0; p < 2; ++p)
                wnv[an][p] = 0.5f * __ldg(&g_wnorm[t * BN + wn * 32 + an * 8 + (lane & 3) * 2 + p]);
    };

    // prologue
    load_chunk(0); CP_COMMIT();
    load_chunk(1); CP_COMMIT();
    load_wn(0);

    int tile = 0;
    const int TOTAL = NTILE * NKC;   // 256
    for (int g = 0; g < TOTAL; ++g) {
        CP_WAIT(1);
        __syncthreads();
        if (g + 2 < TOTAL) load_chunk(g + 2);
        CP_COMMIT();

        const uint32_t base = sb + (uint32_t)(g % STAGES) * STAGE_BYTES;
        #pragma unroll
        for (int ks = 0; ks < 8; ++ks) {
            uint32_t ah[2][4], bh[2][4];
            #pragma unroll
            for (int am = 0; am < 2; ++am) {
                uint32_t ad = base + a_base_row + (uint32_t)(am * 16 * PITCH_B) + lm_off + ks * 32;
                ldsm4(ah[am], ad);
            }
            #pragma unroll
            for (int bp = 0; bp < 2; ++bp) {
                uint32_t bd = base + PLANE_BYTES + b_base_row + (uint32_t)(bp * 16 * PITCH_B) + lm_off + ks * 32;
                ldsm4(bh[bp], bd);
            }
            #pragma unroll
            for (int am = 0; am < 2; ++am)
                #pragma unroll
                for (int an = 0; an < 4; ++an)
                    mma16816(acc[am][an], ah[am], bh[an >> 1][an & 1], bh[an >> 1][(an & 1) + 2]);
        }

        if ((g & (NKC - 1)) == (NKC - 1)) {
            // epilogue: score = dot - 0.5*||w||^2, running top-2
            #pragma unroll
            for (int am = 0; am < 2; ++am)
                #pragma unroll
                for (int an = 0; an < 4; ++an)
                    #pragma unroll
                    for (int j = 0; j < 4; ++j) {
                        int h = j >> 1, p = j & 1;
                        float m = acc[am][an][j] - wnv[an][p];
                        int col = tile * BN + wn * 32 + an * 8 + (lane & 3) * 2 + p;
                        if (m > b1[am][h]) {
                            b2[am][h] = b1[am][h]; i2[am][h] = i1[am][h];
                            b1[am][h] = m;         i1[am][h] = col;
                        } else if (m > b2[am][h]) {
                            b2[am][h] = m;         i2[am][h] = col;
                        }
                        acc[am][an][j] = 0.f;
                    }
            ++tile;
            if (tile < NTILE) load_wn(tile);
        }
    }

    CP_WAIT(0);
    __syncthreads();

    // cross-thread reduction to global top-4: 16 slots x 2 candidates per row
    float* rb1 = reinterpret_cast<float*>(smem);
    float* rb2 = rb1 + BM * 16;
    int*   ri1 = reinterpret_cast<int*>(rb2 + BM * 16);
    int*   ri2 = ri1 + BM * 16;
    #pragma unroll
    for (int am = 0; am < 2; ++am)
        #pragma unroll
        for (int h = 0; h < 2; ++h) {
            int rl = wm * 32 + am * 16 + h * 8 + (lane >> 2);
            int slot = wn * 4 + (lane & 3);
            rb1[rl * 16 + slot] = b1[am][h];
            rb2[rl * 16 + slot] = b2[am][h];
            ri1[rl * 16 + slot] = i1[am][h];
            ri2[rl * 16 + slot] = i2[am][h];
        }
    __syncthreads();
    if (tid < BM) {
        float B[4] = {-3.4e38f, -3.4e38f, -3.4e38f, -3.4e38f};
        int   I[4] = {0, 0, 0, 0};
        #pragma unroll
        for (int s = 0; s < 16; ++s) {
            #pragma unroll
            for (int q = 0; q < 2; ++q) {
                float v = q ? rb2[tid * 16 + s] : rb1[tid * 16 + s];
                int   ii = q ? ri2[tid * 16 + s] : ri1[tid * 16 + s];
                #pragma unroll
                for (int r = 0; r < 4; ++r) {
                    if (v > B[r] || (v == B[r] && ii < I[r])) {
                        #pragma unroll
                        for (int q2 = 3; q2 > r; --q2) { B[q2] = B[q2 - 1]; I[q2] = I[q2 - 1]; }
                        B[r] = v; I[r] = ii;
                        break;
                    }
                }
            }
        }
        g_cand[row0 + tid] = make_int4(I[0], I[1], I[2], I[3]);
    }
}

// ============================================================
// fused fixup + gather + loss:
// one warp per row: fp64 rescore 4 candidates, pick best,
// copy W[best] to out, accumulate sum((q-x)^2)
// ============================================================
__global__ void fixup_gather_kernel(const float* __restrict__ X,
                                    const float* __restrict__ W,
                                    float* __restrict__ out) {
    int row = blockIdx.x * 8 + (threadIdx.x >> 5);
    int lane = threadIdx.x & 31;
    int4 cd = g_cand[row];
    int cand[4] = {cd.x, cd.y, cd.z, cd.w};
    const float* xr = X + (size_t)row * D_DIM;

    double bd = 1e300;
    int bk = 0x7fffffff;
    #pragma unroll
    for (int c = 0; c < 4; ++c) {
        int k = cand[c];
        const float* wr = W + (size_t)k * D_DIM;
        double s = 0.0;
        #pragma unroll
        for (int j = 0; j < 4; ++j) {
            int dd = lane * 4 + j * 128;
            float4 w4 = *reinterpret_cast<const float4*>(wr + dd);
            float4 x4 = *reinterpret_cast<const float4*>(xr + dd);
            s += (double)w4.x * ((double)w4.x - 2.0 * (double)x4.x);
            s += (double)w4.y * ((double)w4.y - 2.0 * (double)x4.y);
            s += (double)w4.z * ((double)w4.z - 2.0 * (double)x4.z);
            s += (double)w4.w * ((double)w4.w - 2.0 * (double)x4.w);
        }
        #pragma unroll
        for (int o = 16; o > 0; o >>= 1)
            s += __shfl_xor_sync(0xffffffffu, s, o);
        // all lanes hold identical s -> identical (bd, bk)
        if (s < bd || (s == bd && k < bk)) { bd = s; bk = k; }
    }

    // gather + loss
    const float* wr = W + (size_t)bk * D_DIM;
    float* orow = out + (size_t)row * D_DIM;
    float s = 0.f;
    #pragma unroll
    for (int j = 0; j < 4; ++j) {
        int dd = lane * 4 + j * 128;
        float4 q  = *reinterpret_cast<const float4*>(wr + dd);
        float4 xv = *reinterpret_cast<const float4*>(xr + dd);
        *reinterpret_cast<float4*>(orow + dd) = q;
        float dx = q.x - xv.x, dy = q.y - xv.y, dz = q.z - xv.z, dw = q.w - xv.w;
        s += dx * dx + dy * dy + dz * dz + dw * dw;
    }
    #pragma unroll
    for (int o = 16; o > 0; o >>= 1) s += __shfl_xor_sync(0xffffffffu, s, o);
    if (lane == 0) atomicAdd(&g_loss, s);
}

__global__ void loss_kernel(float* __restrict__ out, int pos) {
    out[pos] = 1.25f * g_loss / (float)(N_ROWS * D_DIM);
}

// ============================================================
extern "C" void kernel_launch(void* const* d_in, const int* in_sizes, int n_in,
                              void* d_out, int out_size) {
    const float* x = (const float*)d_in[0];
    const float* W = (const float*)d_in[1];
    if (in_sizes[0] == K_CODES * D_DIM && in_sizes[1] == N_ROWS * D_DIM) {
        const float* t = x; x = W; W = t;
    }
    float* out = (float*)d_out;

    cudaFuncSetAttribute(argmin_mma, cudaFuncAttributeMaxDynamicSharedMemorySize, SMEM_DYN);

    split_x_kernel    <<<(N_ROWS * D_DIM / 4) / 256, 256>>>(x);
    split_wnorm_kernel<<<K_CODES, 128>>>(W);
    argmin_mma        <<<N_ROWS / BM, 512, SMEM_DYN>>>();
    fixup_gather_kernel<<<N_ROWS / 8, 256>>>(x, W, out);
    loss_kernel       <<<1, 1>>>(out, out_size - 1);
}